// round 1
// baseline (speedup 1.0000x reference)
#include <cuda_runtime.h>

#define D 128            // DH == DX == 128
#define MAX_M 4096
#define MAX_N 262144

// Scratch (no allocations allowed): proj matrix + segment offsets
__device__ float g_proj[MAX_M * D];
__device__ int   g_offsets[MAX_M + 1];

// ---------------------------------------------------------------------------
// Kernel 1: segment offsets from sorted segment_ids. offsets[g] = first node
// index of segment g; offsets[M] = N. Handles empty segments.
// ---------------------------------------------------------------------------
__global__ void offsets_kernel(const int* __restrict__ seg, int n, int m) {
    int i = blockIdx.x * blockDim.x + threadIdx.x;
    if (i >= n) return;
    int s  = seg[i];
    int sp = (i == 0) ? -1 : seg[i - 1];
    for (int g = sp + 1; g <= s; ++g) g_offsets[g] = i;
    if (i == n - 1) {
        for (int g = s + 1; g <= m; ++g) g_offsets[g] = n;
    }
}

// ---------------------------------------------------------------------------
// Kernel 2: proj = h @ a   (M x 128) = (M x 128)(128 x 128)
// 128 blocks x 128 threads, 32 rows/block. Register tile R=8 x C=4.
// a staged in smem in two 32KB halves (stay <= 48KB static smem),
// h tile (16KB) staged once. h reads are pure smem broadcast; a reads are
// conflict-free float4 (lane = cg, contiguous).
// ---------------------------------------------------------------------------
__global__ __launch_bounds__(128) void proj_kernel(const float* __restrict__ h,
                                                   const float* __restrict__ a) {
    __shared__ float a_sh[64 * D];   // 32 KB (one k-half of a)
    __shared__ float h_sh[32 * D];   // 16 KB (row tile of h)

    int tid = threadIdx.x;
    int cg  = tid & 31;   // column group: 4 cols starting at cg*4
    int rg  = tid >> 5;   // row group: 8 rows starting at rg*8
    int rowBase = blockIdx.x * 32;

    const float4* h4 = (const float4*)h;
    const float4* a4 = (const float4*)a;
    float4* h_sh4 = (float4*)h_sh;
    float4* a_sh4 = (float4*)a_sh;

    for (int idx = tid; idx < 32 * (D / 4); idx += 128)
        h_sh4[idx] = h4[rowBase * (D / 4) + idx];

    float acc[8][4];
#pragma unroll
    for (int r = 0; r < 8; r++)
        acc[r][0] = acc[r][1] = acc[r][2] = acc[r][3] = 0.f;

    for (int half = 0; half < 2; half++) {
        __syncthreads();  // protect a_sh reuse (also covers h_sh load on half 0)
        for (int idx = tid; idx < 64 * (D / 4); idx += 128)
            a_sh4[idx] = a4[half * 64 * (D / 4) + idx];
        __syncthreads();

#pragma unroll 4
        for (int k2 = 0; k2 < 64; k2++) {
            float4 av = *(const float4*)&a_sh[k2 * D + cg * 4];
            int k = half * 64 + k2;
#pragma unroll
            for (int r = 0; r < 8; r++) {
                float hv = h_sh[(rg * 8 + r) * D + k];  // warp-uniform: broadcast
                acc[r][0] += hv * av.x;
                acc[r][1] += hv * av.y;
                acc[r][2] += hv * av.z;
                acc[r][3] += hv * av.w;
            }
        }
    }

    float4* p4 = (float4*)g_proj;
#pragma unroll
    for (int r = 0; r < 8; r++) {
        int row = rowBase + rg * 8 + r;
        p4[row * (D / 4) + cg] =
            make_float4(acc[r][0], acc[r][1], acc[r][2], acc[r][3]);
    }
}

// ---------------------------------------------------------------------------
// Kernel 3: one block per graph. 8 warps, each warp owns one node per step
// (lane l holds float4 of columns 4l..4l+3).
// Pass 1: s_i = <x_i, proj_g>, segment max (x from DRAM).
// Pass 2: recompute s_i (x hits L1/L2), accumulate z and unnormalized e*x.
// Epilogue: out = acc / z. Empty segments write zeros.
// ---------------------------------------------------------------------------
__device__ __forceinline__ float warp_dot(float4 v, float4 p) {
    float d = v.x * p.x + v.y * p.y + v.z * p.z + v.w * p.w;
    d += __shfl_xor_sync(0xffffffffu, d, 16);
    d += __shfl_xor_sync(0xffffffffu, d, 8);
    d += __shfl_xor_sync(0xffffffffu, d, 4);
    d += __shfl_xor_sync(0xffffffffu, d, 2);
    d += __shfl_xor_sync(0xffffffffu, d, 1);
    return d;   // all lanes hold the full dot product
}

__global__ __launch_bounds__(256) void attn_kernel(const float4* __restrict__ x4,
                                                   float* __restrict__ out) {
    int g     = blockIdx.x;
    int start = g_offsets[g];
    int end   = g_offsets[g + 1];
    int tid   = threadIdx.x;

    if (start >= end) {           // empty segment -> zeros (uniform branch)
        if (tid < D) out[g * D + tid] = 0.f;
        return;
    }

    int lane = tid & 31;
    int w    = tid >> 5;

    __shared__ float s_max[8];
    __shared__ float s_z[8];
    __shared__ float s_acc[8 * D];

    const float4* p4 = (const float4*)g_proj;
    float4 p = p4[g * 32 + lane];  // proj row resident in registers

    // ---- pass 1: segment max of scores ----
    float m_w = -3.402823466e38f;
    for (int i = start + w; i < end; i += 8) {
        float4 v = x4[i * 32 + lane];
        float  d = warp_dot(v, p);
        m_w = fmaxf(m_w, d);
    }
    if (lane == 0) s_max[w] = m_w;
    __syncthreads();
    float mg = s_max[0];
#pragma unroll
    for (int j = 1; j < 8; j++) mg = fmaxf(mg, s_max[j]);

    // ---- pass 2: exp-sum and weighted accumulation (x re-read hits cache) ----
    float  z_w = 0.f;
    float4 acc = make_float4(0.f, 0.f, 0.f, 0.f);
    for (int i = start + w; i < end; i += 8) {
        float4 v = x4[i * 32 + lane];
        float  d = warp_dot(v, p);
        float  e = __expf(d - mg);
        z_w   += e;
        acc.x += e * v.x;
        acc.y += e * v.y;
        acc.z += e * v.z;
        acc.w += e * v.w;
    }
    if (lane == 0) s_z[w] = z_w;
    ((float4*)s_acc)[w * 32 + lane] = acc;
    __syncthreads();

    // ---- epilogue: cross-warp reduce + normalize ----
    if (tid < D) {
        float z = 0.f;
#pragma unroll
        for (int j = 0; j < 8; j++) z += s_z[j];
        float v = 0.f;
#pragma unroll
        for (int j = 0; j < 8; j++) v += s_acc[j * D + tid];
        out[g * D + tid] = v / z;
    }
}

// ---------------------------------------------------------------------------
// Launch: inputs per metadata order: h (M*128 f32), x (N*128 f32),
// a (128*128 f32), segment_ids (N int32). Output: M*128 f32.
// ---------------------------------------------------------------------------
extern "C" void kernel_launch(void* const* d_in, const int* in_sizes, int n_in,
                              void* d_out, int out_size) {
    const float* h   = (const float*)d_in[0];
    const float* x   = (const float*)d_in[1];
    const float* a   = (const float*)d_in[2];
    const int*   seg = (const int*)d_in[3];
    float* out = (float*)d_out;

    int m = in_sizes[0] / D;   // 4096
    int n = in_sizes[3];       // 262144

    offsets_kernel<<<(n + 255) / 256, 256>>>(seg, n, m);
    proj_kernel<<<m / 32, 128>>>(h, a);
    attn_kernel<<<m, 256>>>((const float4*)x, out);
}